// round 13
// baseline (speedup 1.0000x reference)
#include <cuda_runtime.h>
#include <cuda_fp16.h>

#define D 128
#define ALPHA 0.1f
#define BETA 0.22314355131420976f        /* log(1.25) */
#define ONE_MB 0.7768564486857909f       /* 1 - BETA */
#define MAXN 50000
#define MAXE 600000
#define SCAN_B 256
#define MAXNB 256

__device__ int   g_deg[MAXN];            // zero at load; re-zeroed every call
__device__ int   g_off[MAXN + 1];
__device__ int   g_cursor[MAXN];
__device__ int   g_csrc[MAXE];
__device__ float g_norm[MAXN];
__device__ uint2 g_feath[MAXN * 32];     // fp16 prescaled feat: row = 256B
__device__ int   g_bsum[MAXNB];
__device__ uint2 g_wperm[16 * 16 * 32];

__device__ __forceinline__ unsigned f2tf32(float f) {
    unsigned r;
    asm("cvt.rna.tf32.f32 %0, %1;" : "=r"(r) : "f"(f));
    return r;
}

// degree count (4 edges/thread); blocks 0..31 also permute W into B-frag order
__global__ void deg_kernel(const int* __restrict__ dst,
                           const float* __restrict__ W, int ne) {
    int tid = threadIdx.x;
    if (blockIdx.x < 32) {
        int t = blockIdx.x * 256 + tid;
        int lane = t & 31, tile = t >> 5;
        int nt = tile & 15, kt = tile >> 4;
        int k = kt * 8 + (lane & 3);
        int nn = nt * 8 + (lane >> 2);
        uint2 b;
        b.x = f2tf32(W[k * D + nn]);
        b.y = f2tf32(W[(k + 4) * D + nn]);
        g_wperm[tile * 32 + lane] = b;
    }
    int base = blockIdx.x * 1024 + tid;
    int d0 = -1, d1 = -1, d2 = -1, d3 = -1;
    if (base       < ne) d0 = dst[base];
    if (base + 256 < ne) d1 = dst[base + 256];
    if (base + 512 < ne) d2 = dst[base + 512];
    if (base + 768 < ne) d3 = dst[base + 768];
    if (d0 >= 0) atomicAdd(&g_deg[d0], 1);
    if (d1 >= 0) atomicAdd(&g_deg[d1], 1);
    if (d2 >= 0) atomicAdd(&g_deg[d2], 1);
    if (d3 >= 0) atomicAdd(&g_deg[d3], 1);
}

// block-local exclusive scan + norm
__global__ void scan_block_kernel(int n) {
    __shared__ int s[SCAN_B];
    int i = blockIdx.x * SCAN_B + threadIdx.x;
    int v = (i < n) ? g_deg[i] : 0;
    s[threadIdx.x] = v;
    __syncthreads();
    #pragma unroll
    for (int off = 1; off < SCAN_B; off <<= 1) {
        int t = (threadIdx.x >= off) ? s[threadIdx.x - off] : 0;
        __syncthreads();
        s[threadIdx.x] += t;
        __syncthreads();
    }
    if (i < n) {
        g_off[i]  = s[threadIdx.x] - v;
        g_norm[i] = rsqrtf(fmaxf((float)v, 1.0f));
    }
    if (threadIdx.x == SCAN_B - 1) g_bsum[blockIdx.x] = s[SCAN_B - 1];
}

// each block reduce-sums bsum[0..bid-1] itself; writes offsets + cursors
__global__ void scan_finish_kernel(int n, int ne) {
    __shared__ int wsum[8];
    int t = threadIdx.x;
    int v = (t < blockIdx.x) ? g_bsum[t] : 0;
    #pragma unroll
    for (int o = 16; o > 0; o >>= 1) v += __shfl_down_sync(0xffffffffu, v, o);
    if ((t & 31) == 0) wsum[t >> 5] = v;
    __syncthreads();
    int prefix = wsum[0] + wsum[1] + wsum[2] + wsum[3]
               + wsum[4] + wsum[5] + wsum[6] + wsum[7];
    int i = blockIdx.x * blockDim.x + t;
    if (i < n) {
        int o = g_off[i] + prefix;
        g_off[i] = o;
        g_cursor[i] = o;
    }
    if (i == 0) g_off[n] = ne;
}

// blocks [0, eb): permute 4 edges/thread + re-zero deg; rest: prescale fp16
__global__ void permute_prescale_kernel(const int* __restrict__ src,
                                        const int* __restrict__ dst,
                                        const float* __restrict__ feat,
                                        int ne, int n, int eb) {
    if ((int)blockIdx.x < eb) {
        int tid = threadIdx.x;
        int base = blockIdx.x * 1024 + tid;
        int s0 = 0, s1 = 0, s2 = 0, s3 = 0;
        int d0 = -1, d1 = -1, d2 = -1, d3 = -1;
        if (base       < ne) { s0 = src[base];       d0 = dst[base]; }
        if (base + 256 < ne) { s1 = src[base + 256]; d1 = dst[base + 256]; }
        if (base + 512 < ne) { s2 = src[base + 512]; d2 = dst[base + 512]; }
        if (base + 768 < ne) { s3 = src[base + 768]; d3 = dst[base + 768]; }
        int p0 = (d0 >= 0) ? atomicAdd(&g_cursor[d0], 1) : 0;
        int p1 = (d1 >= 0) ? atomicAdd(&g_cursor[d1], 1) : 0;
        int p2 = (d2 >= 0) ? atomicAdd(&g_cursor[d2], 1) : 0;
        int p3 = (d3 >= 0) ? atomicAdd(&g_cursor[d3], 1) : 0;
        if (d0 >= 0) g_csrc[p0] = s0;
        if (d1 >= 0) g_csrc[p1] = s1;
        if (d2 >= 0) g_csrc[p2] = s2;
        if (d3 >= 0) g_csrc[p3] = s3;
        if (base < n)       g_deg[base] = 0;
        if (base + 256 < n) g_deg[base + 256] = 0;
        if (base + 512 < n) g_deg[base + 512] = 0;
        if (base + 768 < n) g_deg[base + 768] = 0;
    } else {
        int i = (blockIdx.x - eb) * blockDim.x + threadIdx.x;
        if (i < n * 32) {
            int row = i >> 5;
            float nm = g_norm[row];
            float4 fv = __ldg((const float4*)feat + i);
            __half2 h0 = __floats2half2_rn(fv.x * nm, fv.y * nm);
            __half2 h1 = __floats2half2_rn(fv.z * nm, fv.w * nm);
            uint2 p;
            p.x = *(unsigned*)&h0;
            p.y = *(unsigned*)&h1;
            g_feath[i] = p;
        }
    }
}

// ---- FUSED aggregation + tensor-core GEMM, 512 threads, 4 blocks/SM ----
// Phase 1: paired-lane gathers (lanes 0-15 edge e, 16-31 edge e+1, LDG.128),
//          fp32 accumulate, xor-16 reduce -> fp16 smem tile (17.4KB).
// Phase 2: warp -> (M-tile 16 x N-quarter 32), m16n8k8 tf32 MMA.
#define GROWS 64
#define SH_PAD 136   /* halfs; row = 272B, mod 128B = 16B -> staggered banks */
__global__ __launch_bounds__(512, 4) void fused_mma_kernel(const float* __restrict__ feat0,
                                                           const float* __restrict__ bias,
                                                           float* __restrict__ out, int n) {
    __shared__ __half sh[GROWS][SH_PAD];
    const int tid  = threadIdx.x;
    const int w    = tid >> 5;
    const int lane = tid & 31;
    const int half = lane >> 4;
    const int li   = lane & 15;
    const int r0   = blockIdx.x * GROWS;
    const uint4* f4 = (const uint4*)g_feath;   // row = 16 uint4

    // ---- phase 1: aggregate 4 rows per warp ----
    #pragma unroll
    for (int rr = 0; rr < 4; rr++) {
        int lrow = w * 4 + rr;
        int row  = r0 + lrow;
        float2 a0 = make_float2(0.f, 0.f), a1 = a0, a2 = a0, a3 = a0;
        if (row < n) {
            int beg = g_off[row];
            int end = g_off[row + 1];
            for (int j0 = beg; j0 < end; j0 += 32) {
                int jj = j0 + lane;
                int s = (jj < end) ? g_csrc[jj] : 0;
                int m = min(32, end - j0);
                for (int e = 0; e < m; e += 8) {
                    int e0 = e + half, e1 = e + 2 + half;
                    int e2 = e + 4 + half, e3 = e + 6 + half;
                    int ss0 = __shfl_sync(0xffffffffu, s, min(e0, m - 1));
                    int ss1 = __shfl_sync(0xffffffffu, s, min(e1, m - 1));
                    int ss2 = __shfl_sync(0xffffffffu, s, min(e2, m - 1));
                    int ss3 = __shfl_sync(0xffffffffu, s, min(e3, m - 1));
                    uint4 q0 = make_uint4(0u,0u,0u,0u), q1 = q0, q2 = q0, q3 = q0;
                    if (e0 < m) q0 = __ldg(f4 + (size_t)ss0 * 16 + li);
                    if (e1 < m) q1 = __ldg(f4 + (size_t)ss1 * 16 + li);
                    if (e2 < m) q2 = __ldg(f4 + (size_t)ss2 * 16 + li);
                    if (e3 < m) q3 = __ldg(f4 + (size_t)ss3 * 16 + li);
                    #define ACCUM(q) do { \
                        __half2* ph = (__half2*)&(q); \
                        float2 t0 = __half22float2(ph[0]); \
                        float2 t1 = __half22float2(ph[1]); \
                        float2 t2 = __half22float2(ph[2]); \
                        float2 t3 = __half22float2(ph[3]); \
                        a0.x += t0.x; a0.y += t0.y; \
                        a1.x += t1.x; a1.y += t1.y; \
                        a2.x += t2.x; a2.y += t2.y; \
                        a3.x += t3.x; a3.y += t3.y; } while (0)
                    ACCUM(q0); ACCUM(q1); ACCUM(q2); ACCUM(q3);
                    #undef ACCUM
                }
            }
            // cross-half reduce: lanes li / li+16 hold cols li*8..li*8+7
            a0.x += __shfl_xor_sync(0xffffffffu, a0.x, 16);
            a0.y += __shfl_xor_sync(0xffffffffu, a0.y, 16);
            a1.x += __shfl_xor_sync(0xffffffffu, a1.x, 16);
            a1.y += __shfl_xor_sync(0xffffffffu, a1.y, 16);
            a2.x += __shfl_xor_sync(0xffffffffu, a2.x, 16);
            a2.y += __shfl_xor_sync(0xffffffffu, a2.y, 16);
            a3.x += __shfl_xor_sync(0xffffffffu, a3.x, 16);
            a3.y += __shfl_xor_sync(0xffffffffu, a3.y, 16);

            float nmd = g_norm[row] * (1.0f - ALPHA);
            float4 f0 = __ldg((const float4*)feat0 + (size_t)row * 32 + li * 2 + half);
            float4 v;
            if (half == 0) { v.x = a0.x; v.y = a0.y; v.z = a1.x; v.w = a1.y; }
            else           { v.x = a2.x; v.y = a2.y; v.z = a3.x; v.w = a3.y; }
            v.x = v.x * nmd + f0.x * ALPHA;
            v.y = v.y * nmd + f0.y * ALPHA;
            v.z = v.z * nmd + f0.z * ALPHA;
            v.w = v.w * nmd + f0.w * ALPHA;
            __half2 o0 = __floats2half2_rn(v.x, v.y);
            __half2 o1 = __floats2half2_rn(v.z, v.w);
            uint2 pk;
            pk.x = *(unsigned*)&o0;
            pk.y = *(unsigned*)&o1;
            *(uint2*)&sh[lrow][li * 8 + half * 4] = pk;
        } else {
            *(uint2*)&sh[lrow][li * 8 + half * 4] = make_uint2(0u, 0u);
        }
    }
    __syncthreads();

    // ---- phase 2: MMA. warp -> (M-tile, N-quarter) ----
    const int mw = w & 3;
    const int nq = w >> 2;
    float acc[4][4];
    #pragma unroll
    for (int nt = 0; nt < 4; nt++)
        #pragma unroll
        for (int i = 0; i < 4; i++) acc[nt][i] = 0.f;

    const int ra = mw * 16 + (lane >> 2);
    const int ca = lane & 3;

    #pragma unroll
    for (int kt = 0; kt < 16; kt++) {
        unsigned a0 = f2tf32(__half2float(sh[ra][kt * 8 + ca]));
        unsigned a1 = f2tf32(__half2float(sh[ra + 8][kt * 8 + ca]));
        unsigned a2 = f2tf32(__half2float(sh[ra][kt * 8 + ca + 4]));
        unsigned a3 = f2tf32(__half2float(sh[ra + 8][kt * 8 + ca + 4]));
        const uint2* bp = g_wperm + (kt * 16 + nq * 4) * 32 + lane;
        #pragma unroll
        for (int nt = 0; nt < 4; nt++) {
            uint2 b = __ldg(bp + nt * 32);
            asm volatile(
                "mma.sync.aligned.m16n8k8.row.col.f32.tf32.tf32.f32 "
                "{%0,%1,%2,%3}, {%4,%5,%6,%7}, {%8,%9}, {%0,%1,%2,%3};"
                : "+f"(acc[nt][0]), "+f"(acc[nt][1]),
                  "+f"(acc[nt][2]), "+f"(acc[nt][3])
                : "r"(a0), "r"(a1), "r"(a2), "r"(a3), "r"(b.x), "r"(b.y));
        }
    }

    const int lr   = mw * 16 + (lane >> 2);
    const int row0 = r0 + lr;
    const int col0 = (lane & 3) * 2;
    #pragma unroll
    for (int nt = 0; nt < 4; nt++) {
        int col = nq * 32 + nt * 8 + col0;
        float b0 = __ldg(&bias[col]);
        float b1 = __ldg(&bias[col + 1]);
        if (row0 < n) {
            float2 o;
            o.x = ONE_MB * __half2float(sh[lr][col])     + BETA * acc[nt][0] + b0;
            o.y = ONE_MB * __half2float(sh[lr][col + 1]) + BETA * acc[nt][1] + b1;
            *(float2*)&out[(size_t)row0 * D + col] = o;
        }
        if (row0 + 8 < n) {
            float2 o;
            o.x = ONE_MB * __half2float(sh[lr + 8][col])     + BETA * acc[nt][2] + b0;
            o.y = ONE_MB * __half2float(sh[lr + 8][col + 1]) + BETA * acc[nt][3] + b1;
            *(float2*)&out[(size_t)(row0 + 8) * D + col] = o;
        }
    }
}

extern "C" void kernel_launch(void* const* d_in, const int* in_sizes, int n_in,
                              void* d_out, int out_size) {
    const float* feat  = (const float*)d_in[0];
    const float* feat0 = (const float*)d_in[1];
    const float* W     = (const float*)d_in[2];
    const float* bias  = (const float*)d_in[3];
    const int*   src   = (const int*)d_in[4];
    const int*   dst   = (const int*)d_in[5];
    float* out = (float*)d_out;

    int n  = in_sizes[0] / D;
    int ne = in_sizes[4];
    int nb = (n + SCAN_B - 1) / SCAN_B;          // 196 scan blocks

    int eb4 = (ne + 1023) / 1024;                 // 586 edge blocks
    int degb = (eb4 > 32) ? eb4 : 32;

    deg_kernel<<<degb, 256>>>(dst, W, ne);
    scan_block_kernel<<<nb, SCAN_B>>>(n);
    scan_finish_kernel<<<nb, SCAN_B>>>(n, ne);

    int pb = (n * 32 + 255) / 256;                // prescale blocks
    permute_prescale_kernel<<<eb4 + pb, 256>>>(src, dst, feat, ne, n, eb4);

    fused_mma_kernel<<<(n + GROWS - 1) / GROWS, 512>>>(feat0, bias, out, n);
}

// round 14
// speedup vs baseline: 1.1898x; 1.1898x over previous
#include <cuda_runtime.h>
#include <cuda_fp16.h>

#define D 128
#define ALPHA 0.1f
#define BETA 0.22314355131420976f        /* log(1.25) */
#define ONE_MB 0.7768564486857909f       /* 1 - BETA */
#define MAXN 50000
#define MAXE 600000
#define SCAN_B 256
#define MAXNB 256

__device__ int   g_deg[MAXN];            // zero at load; re-zeroed every call
__device__ int   g_off[MAXN + 1];
__device__ int   g_cursor[MAXN];
__device__ int   g_csrc[MAXE];
__device__ float g_norm[MAXN];
__device__ uint2 g_feath[MAXN * 32];     // fp16 prescaled feat: row = 256B
__device__ int   g_bsum[MAXNB];
__device__ uint2 g_wperm[16 * 16 * 32];

__device__ __forceinline__ unsigned f2tf32(float f) {
    unsigned r;
    asm("cvt.rna.tf32.f32 %0, %1;" : "=r"(r) : "f"(f));
    return r;
}

// degree count (4 edges/thread); blocks 0..31 also permute W into B-frag order
__global__ void deg_kernel(const int* __restrict__ dst,
                           const float* __restrict__ W, int ne) {
    int tid = threadIdx.x;
    if (blockIdx.x < 32) {
        int t = blockIdx.x * 256 + tid;
        int lane = t & 31, tile = t >> 5;
        int nt = tile & 15, kt = tile >> 4;
        int k = kt * 8 + (lane & 3);
        int nn = nt * 8 + (lane >> 2);
        uint2 b;
        b.x = f2tf32(W[k * D + nn]);
        b.y = f2tf32(W[(k + 4) * D + nn]);
        g_wperm[tile * 32 + lane] = b;
    }
    int base = blockIdx.x * 1024 + tid;
    int d0 = -1, d1 = -1, d2 = -1, d3 = -1;
    if (base       < ne) d0 = dst[base];
    if (base + 256 < ne) d1 = dst[base + 256];
    if (base + 512 < ne) d2 = dst[base + 512];
    if (base + 768 < ne) d3 = dst[base + 768];
    if (d0 >= 0) atomicAdd(&g_deg[d0], 1);
    if (d1 >= 0) atomicAdd(&g_deg[d1], 1);
    if (d2 >= 0) atomicAdd(&g_deg[d2], 1);
    if (d3 >= 0) atomicAdd(&g_deg[d3], 1);
}

// block-local exclusive scan + norm
__global__ void scan_block_kernel(int n) {
    __shared__ int s[SCAN_B];
    int i = blockIdx.x * SCAN_B + threadIdx.x;
    int v = (i < n) ? g_deg[i] : 0;
    s[threadIdx.x] = v;
    __syncthreads();
    #pragma unroll
    for (int off = 1; off < SCAN_B; off <<= 1) {
        int t = (threadIdx.x >= off) ? s[threadIdx.x - off] : 0;
        __syncthreads();
        s[threadIdx.x] += t;
        __syncthreads();
    }
    if (i < n) {
        g_off[i]  = s[threadIdx.x] - v;
        g_norm[i] = rsqrtf(fmaxf((float)v, 1.0f));
    }
    if (threadIdx.x == SCAN_B - 1) g_bsum[blockIdx.x] = s[SCAN_B - 1];
}

// each block reduce-sums bsum[0..bid-1] itself; writes offsets + cursors
__global__ void scan_finish_kernel(int n, int ne) {
    __shared__ int wsum[8];
    int t = threadIdx.x;
    int v = (t < blockIdx.x) ? g_bsum[t] : 0;
    #pragma unroll
    for (int o = 16; o > 0; o >>= 1) v += __shfl_down_sync(0xffffffffu, v, o);
    if ((t & 31) == 0) wsum[t >> 5] = v;
    __syncthreads();
    int prefix = wsum[0] + wsum[1] + wsum[2] + wsum[3]
               + wsum[4] + wsum[5] + wsum[6] + wsum[7];
    int i = blockIdx.x * blockDim.x + t;
    if (i < n) {
        int o = g_off[i] + prefix;
        g_off[i] = o;
        g_cursor[i] = o;
    }
    if (i == 0) g_off[n] = ne;
}

// blocks [0, eb): permute 4 edges/thread + re-zero deg; rest: prescale fp16
__global__ void permute_prescale_kernel(const int* __restrict__ src,
                                        const int* __restrict__ dst,
                                        const float* __restrict__ feat,
                                        int ne, int n, int eb) {
    if ((int)blockIdx.x < eb) {
        int tid = threadIdx.x;
        int base = blockIdx.x * 1024 + tid;
        int s0 = 0, s1 = 0, s2 = 0, s3 = 0;
        int d0 = -1, d1 = -1, d2 = -1, d3 = -1;
        if (base       < ne) { s0 = src[base];       d0 = dst[base]; }
        if (base + 256 < ne) { s1 = src[base + 256]; d1 = dst[base + 256]; }
        if (base + 512 < ne) { s2 = src[base + 512]; d2 = dst[base + 512]; }
        if (base + 768 < ne) { s3 = src[base + 768]; d3 = dst[base + 768]; }
        int p0 = (d0 >= 0) ? atomicAdd(&g_cursor[d0], 1) : 0;
        int p1 = (d1 >= 0) ? atomicAdd(&g_cursor[d1], 1) : 0;
        int p2 = (d2 >= 0) ? atomicAdd(&g_cursor[d2], 1) : 0;
        int p3 = (d3 >= 0) ? atomicAdd(&g_cursor[d3], 1) : 0;
        if (d0 >= 0) g_csrc[p0] = s0;
        if (d1 >= 0) g_csrc[p1] = s1;
        if (d2 >= 0) g_csrc[p2] = s2;
        if (d3 >= 0) g_csrc[p3] = s3;
        if (base < n)       g_deg[base] = 0;
        if (base + 256 < n) g_deg[base + 256] = 0;
        if (base + 512 < n) g_deg[base + 512] = 0;
        if (base + 768 < n) g_deg[base + 768] = 0;
    } else {
        int i = (blockIdx.x - eb) * blockDim.x + threadIdx.x;
        if (i < n * 32) {
            int row = i >> 5;
            float nm = g_norm[row];
            float4 fv = __ldg((const float4*)feat + i);
            __half2 h0 = __floats2half2_rn(fv.x * nm, fv.y * nm);
            __half2 h1 = __floats2half2_rn(fv.z * nm, fv.w * nm);
            uint2 p;
            p.x = *(unsigned*)&h0;
            p.y = *(unsigned*)&h1;
            g_feath[i] = p;
        }
    }
}

// ---- FUSED aggregation + tensor-core GEMM, 512 threads / 16 warps, 3 blk/SM ----
// Phase 1: paired-lane gathers — lanes 0-15 edge e, lanes 16-31 edge e+1,
//          LDG.128/lane (1 instr / 2 edges), fp32 accumulate, xor-16 reduce.
// Phase 2: warp -> (M-tile 16 x N-quarter 32), m16n8k8 tf32 MMA.
#define GROWS 64
#define SH_PAD 132   /* mod 32 = 4 -> conflict-free A-frag LDS */
__global__ __launch_bounds__(512, 3) void fused_mma_kernel(const float* __restrict__ feat0,
                                                           const float* __restrict__ bias,
                                                           float* __restrict__ out, int n) {
    __shared__ float sh[GROWS][SH_PAD];
    const int tid  = threadIdx.x;
    const int w    = tid >> 5;
    const int lane = tid & 31;
    const int half = lane >> 4;           // 0 or 1
    const int li   = lane & 15;
    const int r0   = blockIdx.x * GROWS;
    const uint4* f4 = (const uint4*)g_feath;   // row = 16 uint4

    // ---- phase 1: aggregate 4 rows per warp ----
    #pragma unroll
    for (int rr = 0; rr < 4; rr++) {
        int lrow = w * 4 + rr;
        int row  = r0 + lrow;
        if (row < n) {
            float2 a0 = make_float2(0.f, 0.f), a1 = a0, a2 = a0, a3 = a0;
            int beg = g_off[row];
            int end = g_off[row + 1];
            for (int j0 = beg; j0 < end; j0 += 32) {
                int jj = j0 + lane;
                int s = (jj < end) ? g_csrc[jj] : 0;
                int m = min(32, end - j0);
                for (int e = 0; e < m; e += 8) {
                    int e0 = e + half, e1 = e + 2 + half;
                    int e2 = e + 4 + half, e3 = e + 6 + half;
                    int ss0 = __shfl_sync(0xffffffffu, s, min(e0, m - 1));
                    int ss1 = __shfl_sync(0xffffffffu, s, min(e1, m - 1));
                    int ss2 = __shfl_sync(0xffffffffu, s, min(e2, m - 1));
                    int ss3 = __shfl_sync(0xffffffffu, s, min(e3, m - 1));
                    uint4 q0 = make_uint4(0u,0u,0u,0u), q1 = q0, q2 = q0, q3 = q0;
                    if (e0 < m) q0 = __ldg(f4 + (size_t)ss0 * 16 + li);
                    if (e1 < m) q1 = __ldg(f4 + (size_t)ss1 * 16 + li);
                    if (e2 < m) q2 = __ldg(f4 + (size_t)ss2 * 16 + li);
                    if (e3 < m) q3 = __ldg(f4 + (size_t)ss3 * 16 + li);
                    #define ACCUM(q) do { \
                        __half2* ph = (__half2*)&(q); \
                        float2 t0 = __half22float2(ph[0]); \
                        float2 t1 = __half22float2(ph[1]); \
                        float2 t2 = __half22float2(ph[2]); \
                        float2 t3 = __half22float2(ph[3]); \
                        a0.x += t0.x; a0.y += t0.y; \
                        a1.x += t1.x; a1.y += t1.y; \
                        a2.x += t2.x; a2.y += t2.y; \
                        a3.x += t3.x; a3.y += t3.y; } while (0)
                    ACCUM(q0); ACCUM(q1); ACCUM(q2); ACCUM(q3);
                    #undef ACCUM
                }
            }
            // cross-half reduce: lanes li / li+16 hold cols li*8..li*8+7
            a0.x += __shfl_xor_sync(0xffffffffu, a0.x, 16);
            a0.y += __shfl_xor_sync(0xffffffffu, a0.y, 16);
            a1.x += __shfl_xor_sync(0xffffffffu, a1.x, 16);
            a1.y += __shfl_xor_sync(0xffffffffu, a1.y, 16);
            a2.x += __shfl_xor_sync(0xffffffffu, a2.x, 16);
            a2.y += __shfl_xor_sync(0xffffffffu, a2.y, 16);
            a3.x += __shfl_xor_sync(0xffffffffu, a3.x, 16);
            a3.y += __shfl_xor_sync(0xffffffffu, a3.y, 16);

            float nmd = g_norm[row] * (1.0f - ALPHA);
            // lane -> 4 cols: half0 -> li*8+0..3 (a0,a1); half1 -> li*8+4..7 (a2,a3)
            float4 f0 = __ldg((const float4*)feat0 + (size_t)row * 32 + li * 2 + half);
            float4 v;
            if (half == 0) { v.x = a0.x; v.y = a0.y; v.z = a1.x; v.w = a1.y; }
            else           { v.x = a2.x; v.y = a2.y; v.z = a3.x; v.w = a3.y; }
            v.x = v.x * nmd + f0.x * ALPHA;
            v.y = v.y * nmd + f0.y * ALPHA;
            v.z = v.z * nmd + f0.z * ALPHA;
            v.w = v.w * nmd + f0.w * ALPHA;
            *(float4*)&sh[lrow][li * 8 + half * 4] = v;
        } else {
            *(float4*)&sh[lrow][li * 8 + half * 4] = make_float4(0.f, 0.f, 0.f, 0.f);
        }
    }
    __syncthreads();

    // ---- phase 2: MMA. warp -> (M-tile, N-quarter) ----
    const int mw = w & 3;
    const int nq = w >> 2;
    float acc[4][4];
    #pragma unroll
    for (int nt = 0; nt < 4; nt++)
        #pragma unroll
        for (int i = 0; i < 4; i++) acc[nt][i] = 0.f;

    const int ra = mw * 16 + (lane >> 2);
    const int ca = lane & 3;

    #pragma unroll
    for (int kt = 0; kt < 16; kt++) {
        unsigned a0 = f2tf32(sh[ra][kt * 8 + ca]);
        unsigned a1 = f2tf32(sh[ra + 8][kt * 8 + ca]);
        unsigned a2 = f2tf32(sh[ra][kt * 8 + ca + 4]);
        unsigned a3 = f2tf32(sh[ra + 8][kt * 8 + ca + 4]);
        const uint2* bp = g_wperm + (kt * 16 + nq * 4) * 32 + lane;
        #pragma unroll
        for (int nt = 0; nt < 4; nt++) {
            uint2 b = __ldg(bp + nt * 32);
            asm volatile(
                "mma.sync.aligned.m16n8k8.row.col.f32.tf32.tf32.f32 "
                "{%0,%1,%2,%3}, {%4,%5,%6,%7}, {%8,%9}, {%0,%1,%2,%3};"
                : "+f"(acc[nt][0]), "+f"(acc[nt][1]),
                  "+f"(acc[nt][2]), "+f"(acc[nt][3])
                : "r"(a0), "r"(a1), "r"(a2), "r"(a3), "r"(b.x), "r"(b.y));
        }
    }

    const int lr   = mw * 16 + (lane >> 2);
    const int row0 = r0 + lr;
    const int col0 = (lane & 3) * 2;
    #pragma unroll
    for (int nt = 0; nt < 4; nt++) {
        int col = nq * 32 + nt * 8 + col0;
        float b0 = __ldg(&bias[col]);
        float b1 = __ldg(&bias[col + 1]);
        if (row0 < n) {
            float2 o;
            o.x = ONE_MB * sh[lr][col]     + BETA * acc[nt][0] + b0;
            o.y = ONE_MB * sh[lr][col + 1] + BETA * acc[nt][1] + b1;
            *(float2*)&out[(size_t)row0 * D + col] = o;
        }
        if (row0 + 8 < n) {
            float2 o;
            o.x = ONE_MB * sh[lr + 8][col]     + BETA * acc[nt][2] + b0;
            o.y = ONE_MB * sh[lr + 8][col + 1] + BETA * acc[nt][3] + b1;
            *(float2*)&out[(size_t)(row0 + 8) * D + col] = o;
        }
    }
}

extern "C" void kernel_launch(void* const* d_in, const int* in_sizes, int n_in,
                              void* d_out, int out_size) {
    const float* feat  = (const float*)d_in[0];
    const float* feat0 = (const float*)d_in[1];
    const float* W     = (const float*)d_in[2];
    const float* bias  = (const float*)d_in[3];
    const int*   src   = (const int*)d_in[4];
    const int*   dst   = (const int*)d_in[5];
    float* out = (float*)d_out;

    int n  = in_sizes[0] / D;
    int ne = in_sizes[4];
    int nb = (n + SCAN_B - 1) / SCAN_B;          // 196 scan blocks

    int eb4 = (ne + 1023) / 1024;                 // 586 edge blocks
    int degb = (eb4 > 32) ? eb4 : 32;

    deg_kernel<<<degb, 256>>>(dst, W, ne);
    scan_block_kernel<<<nb, SCAN_B>>>(n);
    scan_finish_kernel<<<nb, SCAN_B>>>(n, ne);

    int pb = (n * 32 + 255) / 256;                // prescale blocks
    permute_prescale_kernel<<<eb4 + pb, 256>>>(src, dst, feat, ne, n, eb4);

    fused_mma_kernel<<<(n + GROWS - 1) / GROWS, 512>>>(feat0, bias, out, n);
}

// round 15
// speedup vs baseline: 1.3106x; 1.1016x over previous
#include <cuda_runtime.h>
#include <cuda_fp16.h>

#define D 128
#define ALPHA 0.1f
#define BETA 0.22314355131420976f        /* log(1.25) */
#define ONE_MB 0.7768564486857909f       /* 1 - BETA */
#define MAXN 50000
#define MAXE 600000
#define SCAN_B 256
#define MAXNB 256

__device__ int   g_deg[MAXN];            // zero at load; re-zeroed every call
__device__ int   g_off[MAXN + 1];
__device__ int   g_cursor[MAXN];
__device__ int   g_csrc[MAXE];
__device__ float g_norm[MAXN];
__device__ uint2 g_feath[MAXN * 32];     // fp16 prescaled feat: row = 256B
__device__ int   g_bsum[MAXNB];
__device__ uint2 g_wperm[8 * 16 * 32];   // fp16 B-frags: 8 k-tiles x 16 n-tiles, 32KB

__device__ __forceinline__ unsigned pack_half2(float lo, float hi) {
    __half2 h = __floats2half2_rn(lo, hi);
    return *(unsigned*)&h;
}

// degree count (8 edges/thread); blocks 0..15 also permute W into fp16 B-frag order
__global__ void deg_kernel(const int* __restrict__ dst,
                           const float* __restrict__ W, int ne) {
    int tid = threadIdx.x;
    if (blockIdx.x < 16) {
        int t = blockIdx.x * 256 + tid;   // 4096 lanes: 128 tiles x 32
        int lane = t & 31, tile = t >> 5;
        int nt = tile & 15, kt = tile >> 4;          // kt 0..7
        int k  = kt * 16 + (lane & 3) * 2;
        int nn = nt * 8 + (lane >> 2);
        uint2 b;
        b.x = pack_half2(W[k * D + nn],       W[(k + 1) * D + nn]);
        b.y = pack_half2(W[(k + 8) * D + nn], W[(k + 9) * D + nn]);
        g_wperm[tile * 32 + lane] = b;
    }
    int base = blockIdx.x * 2048 + tid;
    #pragma unroll
    for (int u = 0; u < 8; u++) {
        int e = base + u * 256;
        int d = (e < ne) ? dst[e] : -1;
        if (d >= 0) atomicAdd(&g_deg[d], 1);
    }
}

// block-local exclusive scan + norm
__global__ void scan_block_kernel(int n) {
    __shared__ int s[SCAN_B];
    int i = blockIdx.x * SCAN_B + threadIdx.x;
    int v = (i < n) ? g_deg[i] : 0;
    s[threadIdx.x] = v;
    __syncthreads();
    #pragma unroll
    for (int off = 1; off < SCAN_B; off <<= 1) {
        int t = (threadIdx.x >= off) ? s[threadIdx.x - off] : 0;
        __syncthreads();
        s[threadIdx.x] += t;
        __syncthreads();
    }
    if (i < n) {
        g_off[i]  = s[threadIdx.x] - v;
        g_norm[i] = rsqrtf(fmaxf((float)v, 1.0f));
    }
    if (threadIdx.x == SCAN_B - 1) g_bsum[blockIdx.x] = s[SCAN_B - 1];
}

// each block reduce-sums bsum[0..bid-1] itself; writes offsets + cursors
__global__ void scan_finish_kernel(int n, int ne) {
    __shared__ int wsum[8];
    int t = threadIdx.x;
    int v = (t < blockIdx.x) ? g_bsum[t] : 0;
    #pragma unroll
    for (int o = 16; o > 0; o >>= 1) v += __shfl_down_sync(0xffffffffu, v, o);
    if ((t & 31) == 0) wsum[t >> 5] = v;
    __syncthreads();
    int prefix = wsum[0] + wsum[1] + wsum[2] + wsum[3]
               + wsum[4] + wsum[5] + wsum[6] + wsum[7];
    int i = blockIdx.x * blockDim.x + t;
    if (i < n) {
        int o = g_off[i] + prefix;
        g_off[i] = o;
        g_cursor[i] = o;
    }
    if (i == 0) g_off[n] = ne;
}

// blocks [0, eb): permute 8 edges/thread + re-zero deg; rest: prescale fp16
__global__ void permute_prescale_kernel(const int* __restrict__ src,
                                        const int* __restrict__ dst,
                                        const float* __restrict__ feat,
                                        int ne, int n, int eb) {
    if ((int)blockIdx.x < eb) {
        int tid = threadIdx.x;
        int base = blockIdx.x * 2048 + tid;
        int sv[8], dv[8], pv[8];
        #pragma unroll
        for (int u = 0; u < 8; u++) {
            int e = base + u * 256;
            dv[u] = (e < ne) ? dst[e] : -1;
            sv[u] = (e < ne) ? src[e] : 0;
        }
        #pragma unroll
        for (int u = 0; u < 8; u++)
            pv[u] = (dv[u] >= 0) ? atomicAdd(&g_cursor[dv[u]], 1) : 0;
        #pragma unroll
        for (int u = 0; u < 8; u++)
            if (dv[u] >= 0) g_csrc[pv[u]] = sv[u];
        #pragma unroll
        for (int u = 0; u < 8; u++) {
            int idx = base + u * 256;
            if (idx < n) g_deg[idx] = 0;
        }
    } else {
        int i = (blockIdx.x - eb) * blockDim.x + threadIdx.x;
        if (i < n * 32) {
            int row = i >> 5;
            float nm = g_norm[row];
            float4 fv = __ldg((const float4*)feat + i);
            uint2 p;
            p.x = pack_half2(fv.x * nm, fv.y * nm);
            p.y = pack_half2(fv.z * nm, fv.w * nm);
            g_feath[i] = p;
        }
    }
}

// ---- FUSED aggregation + fp16 tensor-core GEMM, 512 threads, 3 blk/SM ----
// Phase 1: paired-lane gathers (r12-proven), fp32 accumulate, xor-16 reduce,
//          pack fp16 -> smem tile (64 x 128 halfs).
// Phase 2: warp -> (M-tile 16 x N-quarter 32); A via ldmatrix.x4,
//          mma.m16n8k16.f16 with fp32 accumulate (8 kt iterations).
#define GROWS 64
#define SH_PAD 136   /* halfs; 272B row stride -> 4-bank stagger, ldmatrix conflict-free */
__global__ __launch_bounds__(512, 3) void fused_mma_kernel(const float* __restrict__ feat0,
                                                           const float* __restrict__ bias,
                                                           float* __restrict__ out, int n) {
    __shared__ __half sh[GROWS][SH_PAD];
    const int tid  = threadIdx.x;
    const int w    = tid >> 5;
    const int lane = tid & 31;
    const int half = lane >> 4;           // 0 or 1
    const int li   = lane & 15;
    const int r0   = blockIdx.x * GROWS;
    const uint4* f4 = (const uint4*)g_feath;   // row = 16 uint4

    // ---- phase 1: aggregate 4 rows per warp ----
    #pragma unroll
    for (int rr = 0; rr < 4; rr++) {
        int lrow = w * 4 + rr;
        int row  = r0 + lrow;
        if (row < n) {
            float2 a0 = make_float2(0.f, 0.f), a1 = a0, a2 = a0, a3 = a0;
            int beg = g_off[row];
            int end = g_off[row + 1];
            for (int j0 = beg; j0 < end; j0 += 32) {
                int jj = j0 + lane;
                int s = (jj < end) ? g_csrc[jj] : 0;
                int m = min(32, end - j0);
                for (int e = 0; e < m; e += 8) {
                    int e0 = e + half, e1 = e + 2 + half;
                    int e2 = e + 4 + half, e3 = e + 6 + half;
                    int ss0 = __shfl_sync(0xffffffffu, s, min(e0, m - 1));
                    int ss1 = __shfl_sync(0xffffffffu, s, min(e1, m - 1));
                    int ss2 = __shfl_sync(0xffffffffu, s, min(e2, m - 1));
                    int ss3 = __shfl_sync(0xffffffffu, s, min(e3, m - 1));
                    uint4 q0 = make_uint4(0u,0u,0u,0u), q1 = q0, q2 = q0, q3 = q0;
                    if (e0 < m) q0 = __ldg(f4 + (size_t)ss0 * 16 + li);
                    if (e1 < m) q1 = __ldg(f4 + (size_t)ss1 * 16 + li);
                    if (e2 < m) q2 = __ldg(f4 + (size_t)ss2 * 16 + li);
                    if (e3 < m) q3 = __ldg(f4 + (size_t)ss3 * 16 + li);
                    #define ACCUM(q) do { \
                        __half2* ph = (__half2*)&(q); \
                        float2 t0 = __half22float2(ph[0]); \
                        float2 t1 = __half22float2(ph[1]); \
                        float2 t2 = __half22float2(ph[2]); \
                        float2 t3 = __half22float2(ph[3]); \
                        a0.x += t0.x; a0.y += t0.y; \
                        a1.x += t1.x; a1.y += t1.y; \
                        a2.x += t2.x; a2.y += t2.y; \
                        a3.x += t3.x; a3.y += t3.y; } while (0)
                    ACCUM(q0); ACCUM(q1); ACCUM(q2); ACCUM(q3);
                    #undef ACCUM
                }
            }
            a0.x += __shfl_xor_sync(0xffffffffu, a0.x, 16);
            a0.y += __shfl_xor_sync(0xffffffffu, a0.y, 16);
            a1.x += __shfl_xor_sync(0xffffffffu, a1.x, 16);
            a1.y += __shfl_xor_sync(0xffffffffu, a1.y, 16);
            a2.x += __shfl_xor_sync(0xffffffffu, a2.x, 16);
            a2.y += __shfl_xor_sync(0xffffffffu, a2.y, 16);
            a3.x += __shfl_xor_sync(0xffffffffu, a3.x, 16);
            a3.y += __shfl_xor_sync(0xffffffffu, a3.y, 16);

            float nmd = g_norm[row] * (1.0f - ALPHA);
            float4 f0 = __ldg((const float4*)feat0 + (size_t)row * 32 + li * 2 + half);
            float4 v;
            if (half == 0) { v.x = a0.x; v.y = a0.y; v.z = a1.x; v.w = a1.y; }
            else           { v.x = a2.x; v.y = a2.y; v.z = a3.x; v.w = a3.y; }
            v.x = v.x * nmd + f0.x * ALPHA;
            v.y = v.y * nmd + f0.y * ALPHA;
            v.z = v.z * nmd + f0.z * ALPHA;
            v.w = v.w * nmd + f0.w * ALPHA;
            uint2 pk;
            pk.x = pack_half2(v.x, v.y);
            pk.y = pack_half2(v.z, v.w);
            *(uint2*)&sh[lrow][li * 8 + half * 4] = pk;
        } else {
            *(uint2*)&sh[lrow][li * 8 + half * 4] = make_uint2(0u, 0u);
        }
    }
    __syncthreads();

    // ---- phase 2: fp16 MMA. warp -> (M-tile mw, N-quarter nq) ----
    const int mw = w & 3;
    const int nq = w >> 2;
    float acc[4][4];
    #pragma unroll
    for (int nt = 0; nt < 4; nt++)
        #pragma unroll
        for (int i = 0; i < 4; i++) acc[nt][i] = 0.f;

    // ldmatrix source address: lanes 0-15 -> rows, lanes 16-31 -> rows with col+8
    const int lm_row = mw * 16 + (lane & 15);
    const int lm_colh = (lane >> 4) * 8;

    #pragma unroll
    for (int kt = 0; kt < 8; kt++) {
        unsigned a0, a1, a2, a3;
        {
            unsigned addr = (unsigned)__cvta_generic_to_shared(
                &sh[lm_row][kt * 16 + lm_colh]);
            asm volatile(
                "ldmatrix.sync.aligned.m8n8.x4.shared.b16 {%0,%1,%2,%3}, [%4];"
                : "=r"(a0), "=r"(a1), "=r"(a2), "=r"(a3) : "r"(addr));
        }
        const uint2* bp = g_wperm + (kt * 16 + nq * 4) * 32 + lane;
        #pragma unroll
        for (int nt = 0; nt < 4; nt++) {
            uint2 b = __ldg(bp + nt * 32);
            asm volatile(
                "mma.sync.aligned.m16n8k16.row.col.f32.f16.f16.f32 "
                "{%0,%1,%2,%3}, {%4,%5,%6,%7}, {%8,%9}, {%0,%1,%2,%3};"
                : "+f"(acc[nt][0]), "+f"(acc[nt][1]),
                  "+f"(acc[nt][2]), "+f"(acc[nt][3])
                : "r"(a0), "r"(a1), "r"(a2), "r"(a3), "r"(b.x), "r"(b.y));
        }
    }

    // epilogue: out = (1-beta)*h + beta*acc + bias
    const int lr   = mw * 16 + (lane >> 2);
    const int row0 = r0 + lr;
    const int col0 = (lane & 3) * 2;
    #pragma unroll
    for (int nt = 0; nt < 4; nt++) {
        int col = nq * 32 + nt * 8 + col0;
        float b0 = __ldg(&bias[col]);
        float b1 = __ldg(&bias[col + 1]);
        if (row0 < n) {
            float2 o;
            o.x = ONE_MB * __half2float(sh[lr][col])     + BETA * acc[nt][0] + b0;
            o.y = ONE_MB * __half2float(sh[lr][col + 1]) + BETA * acc[nt][1] + b1;
            *(float2*)&out[(size_t)row0 * D + col] = o;
        }
        if (row0 + 8 < n) {
            float2 o;
            o.x = ONE_MB * __half2float(sh[lr + 8][col])     + BETA * acc[nt][2] + b0;
            o.y = ONE_MB * __half2float(sh[lr + 8][col + 1]) + BETA * acc[nt][3] + b1;
            *(float2*)&out[(size_t)(row0 + 8) * D + col] = o;
        }
    }
}

extern "C" void kernel_launch(void* const* d_in, const int* in_sizes, int n_in,
                              void* d_out, int out_size) {
    const float* feat  = (const float*)d_in[0];
    const float* feat0 = (const float*)d_in[1];
    const float* W     = (const float*)d_in[2];
    const float* bias  = (const float*)d_in[3];
    const int*   src   = (const int*)d_in[4];
    const int*   dst   = (const int*)d_in[5];
    float* out = (float*)d_out;

    int n  = in_sizes[0] / D;
    int ne = in_sizes[4];
    int nb = (n + SCAN_B - 1) / SCAN_B;          // 196 scan blocks

    int eb8 = (ne + 2047) / 2048;                 // 293 edge blocks (8 edges/thread)
    int degb = (eb8 > 16) ? eb8 : 16;

    deg_kernel<<<degb, 256>>>(dst, W, ne);
    scan_block_kernel<<<nb, SCAN_B>>>(n);
    scan_finish_kernel<<<nb, SCAN_B>>>(n, ne);

    int pb = (n * 32 + 255) / 256;                // prescale blocks
    permute_prescale_kernel<<<eb8 + pb, 256>>>(src, dst, feat, ne, n, eb8);

    fused_mma_kernel<<<(n + GROWS - 1) / GROWS, 512>>>(feat0, bias, out, n);
}

// round 16
// speedup vs baseline: 1.4072x; 1.0737x over previous
#include <cuda_runtime.h>
#include <cuda_fp16.h>

#define D 128
#define ALPHA 0.1f
#define BETA 0.22314355131420976f        /* log(1.25) */
#define ONE_MB 0.7768564486857909f       /* 1 - BETA */
#define MAXN 50000
#define MAXE 600000

__device__ int   g_deg[MAXN];            // zero at load; re-zeroed every call
__device__ int2  g_range[MAXN];          // per-row [beg, end) in csrc
__device__ int   g_cursor[MAXN];
__device__ int   g_csrc[MAXE];
__device__ float g_norm[MAXN];
__device__ uint2 g_feath[MAXN * 32];     // fp16 prescaled feat: row = 256B
__device__ uint2 g_wperm[8 * 16 * 32];   // fp16 B-frags: 8 k-tiles x 16 n-tiles
__device__ unsigned g_alloc_ctr;         // reset by deg_kernel each call

__device__ __forceinline__ unsigned pack_half2(float lo, float hi) {
    __half2 h = __floats2half2_rn(lo, hi);
    return *(unsigned*)&h;
}

// degree count (4 edges/thread); blocks 0..15 also permute W into fp16 B-frag order
__global__ void deg_kernel(const int* __restrict__ dst,
                           const float* __restrict__ W, int ne) {
    int tid = threadIdx.x;
    if (blockIdx.x == 0 && tid == 0) g_alloc_ctr = 0u;
    if (blockIdx.x < 16) {
        int t = blockIdx.x * 256 + tid;   // 4096 lanes: 128 tiles x 32
        int lane = t & 31, tile = t >> 5;
        int nt = tile & 15, kt = tile >> 4;
        int k  = kt * 16 + (lane & 3) * 2;
        int nn = nt * 8 + (lane >> 2);
        uint2 b;
        b.x = pack_half2(W[k * D + nn],       W[(k + 1) * D + nn]);
        b.y = pack_half2(W[(k + 8) * D + nn], W[(k + 9) * D + nn]);
        g_wperm[tile * 32 + lane] = b;
    }
    int base = blockIdx.x * 1024 + tid;
    int d0 = -1, d1 = -1, d2 = -1, d3 = -1;
    if (base       < ne) d0 = dst[base];
    if (base + 256 < ne) d1 = dst[base + 256];
    if (base + 512 < ne) d2 = dst[base + 512];
    if (base + 768 < ne) d3 = dst[base + 768];
    if (d0 >= 0) atomicAdd(&g_deg[d0], 1);
    if (d1 >= 0) atomicAdd(&g_deg[d1], 1);
    if (d2 >= 0) atomicAdd(&g_deg[d2], 1);
    if (d3 >= 0) atomicAdd(&g_deg[d3], 1);
}

// blocks [0, ab): range allocation (1 atomic per block) + norm
// blocks [ab, ..): prescale feat*norm -> fp16 (norm recomputed from deg)
__global__ __launch_bounds__(256) void alloc_prescale_kernel(const float* __restrict__ feat,
                                                             int n, int ab) {
    if ((int)blockIdx.x < ab) {
        __shared__ int wsums[8];
        __shared__ int sbase;
        const int tid  = threadIdx.x;
        const int lane = tid & 31;
        const int wid  = tid >> 5;
        const int i = blockIdx.x * 256 + tid;

        int d = (i < n) ? g_deg[i] : 0;
        // warp inclusive scan
        int incl = d;
        #pragma unroll
        for (int o = 1; o < 32; o <<= 1) {
            int t = __shfl_up_sync(0xffffffffu, incl, o);
            if (lane >= o) incl += t;
        }
        if (lane == 31) wsums[wid] = incl;
        __syncthreads();
        if (tid == 0) {
            int t = 0;
            #pragma unroll
            for (int j = 0; j < 8; j++) { int v = wsums[j]; wsums[j] = t; t += v; }
            sbase = (int)atomicAdd(&g_alloc_ctr, (unsigned)t);
        }
        __syncthreads();
        if (i < n) {
            int beg = sbase + wsums[wid] + incl - d;
            g_range[i] = make_int2(beg, beg + d);
            g_cursor[i] = beg;
            g_norm[i] = rsqrtf(fmaxf((float)d, 1.0f));
        }
    } else {
        int i = (blockIdx.x - ab) * blockDim.x + threadIdx.x;
        if (i < n * 32) {
            int row = i >> 5;
            float nm = rsqrtf(fmaxf((float)g_deg[row], 1.0f));
            float4 fv = __ldg((const float4*)feat + i);
            uint2 p;
            p.x = pack_half2(fv.x * nm, fv.y * nm);
            p.y = pack_half2(fv.z * nm, fv.w * nm);
            g_feath[i] = p;
        }
    }
}

// permute 4 edges/thread into CSR ranges + re-zero deg for next replay
__global__ void permute_kernel(const int* __restrict__ src,
                               const int* __restrict__ dst, int ne, int n) {
    int tid = threadIdx.x;
    int base = blockIdx.x * 1024 + tid;
    int s0 = 0, s1 = 0, s2 = 0, s3 = 0;
    int d0 = -1, d1 = -1, d2 = -1, d3 = -1;
    if (base       < ne) { s0 = src[base];       d0 = dst[base]; }
    if (base + 256 < ne) { s1 = src[base + 256]; d1 = dst[base + 256]; }
    if (base + 512 < ne) { s2 = src[base + 512]; d2 = dst[base + 512]; }
    if (base + 768 < ne) { s3 = src[base + 768]; d3 = dst[base + 768]; }
    int p0 = (d0 >= 0) ? atomicAdd(&g_cursor[d0], 1) : 0;
    int p1 = (d1 >= 0) ? atomicAdd(&g_cursor[d1], 1) : 0;
    int p2 = (d2 >= 0) ? atomicAdd(&g_cursor[d2], 1) : 0;
    int p3 = (d3 >= 0) ? atomicAdd(&g_cursor[d3], 1) : 0;
    if (d0 >= 0) g_csrc[p0] = s0;
    if (d1 >= 0) g_csrc[p1] = s1;
    if (d2 >= 0) g_csrc[p2] = s2;
    if (d3 >= 0) g_csrc[p3] = s3;
    if (base < n)       g_deg[base] = 0;
    if (base + 256 < n) g_deg[base + 256] = 0;
    if (base + 512 < n) g_deg[base + 512] = 0;
    if (base + 768 < n) g_deg[base + 768] = 0;
}

// ---- FUSED aggregation + fp16 tensor-core GEMM, 512 threads, 3 blk/SM ----
// Phase 1: paired-lane gathers, first-level fp16 hadd2 tree, fp32 accumulate,
//          xor-16 reduce -> fp16 smem tile.
// Phase 2: A via ldmatrix.x4, mma.m16n8k16.f16 fp32-accumulate (8 kt iters).
#define GROWS 64
#define SH_PAD 136   /* halfs; 272B row stride -> conflict-free ldmatrix */
__global__ __launch_bounds__(512, 3) void fused_mma_kernel(const float* __restrict__ feat0,
                                                           const float* __restrict__ bias,
                                                           float* __restrict__ out, int n) {
    __shared__ __half sh[GROWS][SH_PAD];
    const int tid  = threadIdx.x;
    const int w    = tid >> 5;
    const int lane = tid & 31;
    const int half = lane >> 4;
    const int li   = lane & 15;
    const int r0   = blockIdx.x * GROWS;
    const uint4* f4 = (const uint4*)g_feath;

    #pragma unroll
    for (int rr = 0; rr < 4; rr++) {
        int lrow = w * 4 + rr;
        int row  = r0 + lrow;
        if (row < n) {
            float2 a0 = make_float2(0.f, 0.f), a1 = a0, a2 = a0, a3 = a0;
            int2 rng = g_range[row];
            for (int j0 = rng.x; j0 < rng.y; j0 += 32) {
                int jj = j0 + lane;
                int s = (jj < rng.y) ? g_csrc[jj] : 0;
                int m = min(32, rng.y - j0);
                for (int e = 0; e < m; e += 8) {
                    int e0 = e + half, e1 = e + 2 + half;
                    int e2 = e + 4 + half, e3 = e + 6 + half;
                    int ss0 = __shfl_sync(0xffffffffu, s, min(e0, m - 1));
                    int ss1 = __shfl_sync(0xffffffffu, s, min(e1, m - 1));
                    int ss2 = __shfl_sync(0xffffffffu, s, min(e2, m - 1));
                    int ss3 = __shfl_sync(0xffffffffu, s, min(e3, m - 1));
                    uint4 q0 = make_uint4(0u,0u,0u,0u), q1 = q0, q2 = q0, q3 = q0;
                    if (e0 < m) q0 = __ldg(f4 + (size_t)ss0 * 16 + li);
                    if (e1 < m) q1 = __ldg(f4 + (size_t)ss1 * 16 + li);
                    if (e2 < m) q2 = __ldg(f4 + (size_t)ss2 * 16 + li);
                    if (e3 < m) q3 = __ldg(f4 + (size_t)ss3 * 16 + li);
                    // first-level fp16 pair tree, then fp32 accumulate
                    __half2* h0 = (__half2*)&q0;
                    __half2* h1 = (__half2*)&q1;
                    __half2* h2 = (__half2*)&q2;
                    __half2* h3 = (__half2*)&q3;
                    #pragma unroll
                    for (int c = 0; c < 4; c++) {
                        __half2 r01 = __hadd2(h0[c], h1[c]);
                        __half2 r23 = __hadd2(h2[c], h3[c]);
                        float2 f01 = __half22float2(r01);
                        float2 f23 = __half22float2(r23);
                        float2* ac = (c == 0) ? &a0 : (c == 1) ? &a1 : (c == 2) ? &a2 : &a3;
                        ac->x += f01.x + f23.x;
                        ac->y += f01.y + f23.y;
                    }
                }
            }
            a0.x += __shfl_xor_sync(0xffffffffu, a0.x, 16);
            a0.y += __shfl_xor_sync(0xffffffffu, a0.y, 16);
            a1.x += __shfl_xor_sync(0xffffffffu, a1.x, 16);
            a1.y += __shfl_xor_sync(0xffffffffu, a1.y, 16);
            a2.x += __shfl_xor_sync(0xffffffffu, a2.x, 16);
            a2.y += __shfl_xor_sync(0xffffffffu, a2.y, 16);
            a3.x += __shfl_xor_sync(0xffffffffu, a3.x, 16);
            a3.y += __shfl_xor_sync(0xffffffffu, a3.y, 16);

            float nmd = g_norm[row] * (1.0f - ALPHA);
            float4 f0 = __ldg((const float4*)feat0 + (size_t)row * 32 + li * 2 + half);
            float4 v;
            if (half == 0) { v.x = a0.x; v.y = a0.y; v.z = a1.x; v.w = a1.y; }
            else           { v.x = a2.x; v.y = a2.y; v.z = a3.x; v.w = a3.y; }
            v.x = v.x * nmd + f0.x * ALPHA;
            v.y = v.y * nmd + f0.y * ALPHA;
            v.z = v.z * nmd + f0.z * ALPHA;
            v.w = v.w * nmd + f0.w * ALPHA;
            uint2 pk;
            pk.x = pack_half2(v.x, v.y);
            pk.y = pack_half2(v.z, v.w);
            *(uint2*)&sh[lrow][li * 8 + half * 4] = pk;
        } else {
            *(uint2*)&sh[lrow][li * 8 + half * 4] = make_uint2(0u, 0u);
        }
    }
    __syncthreads();

    // ---- phase 2: fp16 MMA ----
    const int mw = w & 3;
    const int nq = w >> 2;
    float acc[4][4];
    #pragma unroll
    for (int nt = 0; nt < 4; nt++)
        #pragma unroll
        for (int i = 0; i < 4; i++) acc[nt][i] = 0.f;

    const int lm_row = mw * 16 + (lane & 15);
    const int lm_colh = (lane >> 4) * 8;

    #pragma unroll
    for (int kt = 0; kt < 8; kt++) {
        unsigned a0, a1, a2, a3;
        {
            unsigned addr = (unsigned)__cvta_generic_to_shared(
                &sh[lm_row][kt * 16 + lm_colh]);
            asm volatile(
                "ldmatrix.sync.aligned.m8n8.x4.shared.b16 {%0,%1,%2,%3}, [%4];"
                : "=r"(a0), "=r"(a1), "=r"(a2), "=r"(a3) : "r"(addr));
        }
        const uint2* bp = g_wperm + (kt * 16 + nq * 4) * 32 + lane;
        #pragma unroll
        for (int nt = 0; nt < 4; nt++) {
            uint2 b = __ldg(bp + nt * 32);
            asm volatile(
                "mma.sync.aligned.m16n8k16.row.col.f32.f16.f16.f32 "
                "{%0,%1,%2,%3}, {%4,%5,%6,%7}, {%8,%9}, {%0,%1,%2,%3};"
                : "+f"(acc[nt][0]), "+f"(acc[nt][1]),
                  "+f"(acc[nt][2]), "+f"(acc[nt][3])
                : "r"(a0), "r"(a1), "r"(a2), "r"(a3), "r"(b.x), "r"(b.y));
        }
    }

    const int lr   = mw * 16 + (lane >> 2);
    const int row0 = r0 + lr;
    const int col0 = (lane & 3) * 2;
    #pragma unroll
    for (int nt = 0; nt < 4; nt++) {
        int col = nq * 32 + nt * 8 + col0;
        float b0 = __ldg(&bias[col]);
        float b1 = __ldg(&bias[col + 1]);
        if (row0 < n) {
            float2 o;
            o.x = ONE_MB * __half2float(sh[lr][col])     + BETA * acc[nt][0] + b0;
            o.y = ONE_MB * __half2float(sh[lr][col + 1]) + BETA * acc[nt][1] + b1;
            *(float2*)&out[(size_t)row0 * D + col] = o;
        }
        if (row0 + 8 < n) {
            float2 o;
            o.x = ONE_MB * __half2float(sh[lr + 8][col])     + BETA * acc[nt][2] + b0;
            o.y = ONE_MB * __half2float(sh[lr + 8][col + 1]) + BETA * acc[nt][3] + b1;
            *(float2*)&out[(size_t)(row0 + 8) * D + col] = o;
        }
    }
}

extern "C" void kernel_launch(void* const* d_in, const int* in_sizes, int n_in,
                              void* d_out, int out_size) {
    const float* feat  = (const float*)d_in[0];
    const float* feat0 = (const float*)d_in[1];
    const float* W     = (const float*)d_in[2];
    const float* bias  = (const float*)d_in[3];
    const int*   src   = (const int*)d_in[4];
    const int*   dst   = (const int*)d_in[5];
    float* out = (float*)d_out;

    int n  = in_sizes[0] / D;
    int ne = in_sizes[4];

    int eb4 = (ne + 1023) / 1024;                 // 586 edge blocks
    int degb = (eb4 > 16) ? eb4 : 16;

    deg_kernel<<<degb, 256>>>(dst, W, ne);

    int ab = (n + 255) / 256;                     // 196 allocator blocks
    int pb = (n * 32 + 255) / 256;                // 6250 prescale blocks
    alloc_prescale_kernel<<<ab + pb, 256>>>(feat, n, ab);

    permute_kernel<<<eb4, 256>>>(src, dst, ne, n);

    fused_mma_kernel<<<(n + GROWS - 1) / GROWS, 512>>>(feat0, bias, out, n);
}

// round 17
// speedup vs baseline: 1.4226x; 1.0110x over previous
#include <cuda_runtime.h>
#include <cuda_fp16.h>

#define D 128
#define ALPHA 0.1f
#define BETA 0.22314355131420976f        /* log(1.25) */
#define ONE_MB 0.7768564486857909f       /* 1 - BETA */
#define MAXN 50000
#define MAXE2 1000096                    /* padded CSR capacity + slack */

__device__ int   g_deg[MAXN];            // zero at load; re-zeroed every call
__device__ int2  g_range[MAXN];          // per-row [beg, beg+deg_pad)
__device__ int   g_cursor[MAXN];
__device__ int   g_csrc[MAXE2];
__device__ float g_norm[MAXN];
__device__ uint2 g_feath[(MAXN + 1) * 32];  // fp16 prescaled feat; row MAXN stays ZERO (pad row)
__device__ uint2 g_wperm[8 * 16 * 32];   // fp16 B-frags: 8 k-tiles x 16 n-tiles
__device__ unsigned g_alloc_ctr;         // reset by deg_kernel each call

__device__ __forceinline__ unsigned pack_half2(float lo, float hi) {
    __half2 h = __floats2half2_rn(lo, hi);
    return *(unsigned*)&h;
}

// degree count (4 edges/thread); blocks 0..15 also permute W into fp16 B-frag order
__global__ void deg_kernel(const int* __restrict__ dst,
                           const float* __restrict__ W, int ne) {
    int tid = threadIdx.x;
    if (blockIdx.x == 0 && tid == 0) g_alloc_ctr = 0u;
    if (blockIdx.x < 16) {
        int t = blockIdx.x * 256 + tid;   // 4096 lanes: 128 tiles x 32
        int lane = t & 31, tile = t >> 5;
        int nt = tile & 15, kt = tile >> 4;
        int k  = kt * 16 + (lane & 3) * 2;
        int nn = nt * 8 + (lane >> 2);
        uint2 b;
        b.x = pack_half2(W[k * D + nn],       W[(k + 1) * D + nn]);
        b.y = pack_half2(W[(k + 8) * D + nn], W[(k + 9) * D + nn]);
        g_wperm[tile * 32 + lane] = b;
    }
    int base = blockIdx.x * 1024 + tid;
    int d0 = -1, d1 = -1, d2 = -1, d3 = -1;
    if (base       < ne) d0 = dst[base];
    if (base + 256 < ne) d1 = dst[base + 256];
    if (base + 512 < ne) d2 = dst[base + 512];
    if (base + 768 < ne) d3 = dst[base + 768];
    if (d0 >= 0) atomicAdd(&g_deg[d0], 1);
    if (d1 >= 0) atomicAdd(&g_deg[d1], 1);
    if (d2 >= 0) atomicAdd(&g_deg[d2], 1);
    if (d3 >= 0) atomicAdd(&g_deg[d3], 1);
}

// blocks [0, ab): padded range allocation (1 atomic/block) + norm + pad fill
// blocks [ab, ..): prescale feat*norm -> fp16
__global__ __launch_bounds__(256) void alloc_prescale_kernel(const float* __restrict__ feat,
                                                             int n, int ab) {
    if ((int)blockIdx.x < ab) {
        __shared__ int wsums[8];
        __shared__ int sbase;
        const int tid  = threadIdx.x;
        const int lane = tid & 31;
        const int wid  = tid >> 5;
        const int i = blockIdx.x * 256 + tid;

        int d  = (i < n) ? g_deg[i] : 0;
        int dp = (d + 7) & ~7;            // pad to multiple of 8
        int incl = dp;
        #pragma unroll
        for (int o = 1; o < 32; o <<= 1) {
            int t = __shfl_up_sync(0xffffffffu, incl, o);
            if (lane >= o) incl += t;
        }
        if (lane == 31) wsums[wid] = incl;
        __syncthreads();
        if (tid == 0) {
            int t = 0;
            #pragma unroll
            for (int j = 0; j < 8; j++) { int v = wsums[j]; wsums[j] = t; t += v; }
            sbase = (int)atomicAdd(&g_alloc_ctr, (unsigned)t);
        }
        __syncthreads();
        if (i < n) {
            int beg = sbase + wsums[wid] + incl - dp;
            g_range[i] = make_int2(beg, beg + dp);
            g_cursor[i] = beg;
            g_norm[i] = rsqrtf(fmaxf((float)d, 1.0f));
            for (int j = beg + d; j < beg + dp; j++) g_csrc[j] = n;  // pad -> zero row
        }
    } else {
        int i = (blockIdx.x - ab) * blockDim.x + threadIdx.x;
        if (i < n * 32) {
            int row = i >> 5;
            float nm = rsqrtf(fmaxf((float)g_deg[row], 1.0f));
            float4 fv = __ldg((const float4*)feat + i);
            uint2 p;
            p.x = pack_half2(fv.x * nm, fv.y * nm);
            p.y = pack_half2(fv.z * nm, fv.w * nm);
            g_feath[i] = p;
        }
    }
}

// permute 4 edges/thread into CSR ranges + re-zero deg for next replay
__global__ void permute_kernel(const int* __restrict__ src,
                               const int* __restrict__ dst, int ne, int n) {
    int tid = threadIdx.x;
    int base = blockIdx.x * 1024 + tid;
    int s0 = 0, s1 = 0, s2 = 0, s3 = 0;
    int d0 = -1, d1 = -1, d2 = -1, d3 = -1;
    if (base       < ne) { s0 = src[base];       d0 = dst[base]; }
    if (base + 256 < ne) { s1 = src[base + 256]; d1 = dst[base + 256]; }
    if (base + 512 < ne) { s2 = src[base + 512]; d2 = dst[base + 512]; }
    if (base + 768 < ne) { s3 = src[base + 768]; d3 = dst[base + 768]; }
    int p0 = (d0 >= 0) ? atomicAdd(&g_cursor[d0], 1) : 0;
    int p1 = (d1 >= 0) ? atomicAdd(&g_cursor[d1], 1) : 0;
    int p2 = (d2 >= 0) ? atomicAdd(&g_cursor[d2], 1) : 0;
    int p3 = (d3 >= 0) ? atomicAdd(&g_cursor[d3], 1) : 0;
    if (d0 >= 0) g_csrc[p0] = s0;
    if (d1 >= 0) g_csrc[p1] = s1;
    if (d2 >= 0) g_csrc[p2] = s2;
    if (d3 >= 0) g_csrc[p3] = s3;
    if (base < n)       g_deg[base] = 0;
    if (base + 256 < n) g_deg[base + 256] = 0;
    if (base + 512 < n) g_deg[base + 512] = 0;
    if (base + 768 < n) g_deg[base + 768] = 0;
}

// ---- FUSED aggregation + fp16 tensor-core GEMM, 512 threads, 3 blk/SM ----
// Phase 1: guard-free paired-lane gathers (CSR padded to 8; dummy row = zeros),
//          fp16 first-level tree, fp32 accumulate, xor-16 reduce -> fp16 tile.
// Phase 2: A via ldmatrix.x4, mma.m16n8k16.f16 fp32-accumulate (8 kt iters).
#define GROWS 64
#define SH_PAD 136   /* halfs; 272B row stride -> conflict-free ldmatrix */
__global__ __launch_bounds__(512, 3) void fused_mma_kernel(const float* __restrict__ feat0,
                                                           const float* __restrict__ bias,
                                                           float* __restrict__ out, int n) {
    __shared__ __half sh[GROWS][SH_PAD];
    const int tid  = threadIdx.x;
    const int w    = tid >> 5;
    const int lane = tid & 31;
    const int half = lane >> 4;
    const int li   = lane & 15;
    const int r0   = blockIdx.x * GROWS;
    const uint4* f4 = (const uint4*)g_feath;

    #pragma unroll
    for (int rr = 0; rr < 4; rr++) {
        int lrow = w * 4 + rr;
        int row  = r0 + lrow;
        if (row < n) {
            float2 a0 = make_float2(0.f, 0.f), a1 = a0, a2 = a0, a3 = a0;
            int2 rng = g_range[row];
            for (int j0 = rng.x; j0 < rng.y; j0 += 32) {
                int s = g_csrc[j0 + lane];            // unconditional (array slack)
                int m = min(32, rng.y - j0);          // multiple of 8
                for (int e = 0; e < m; e += 8) {
                    int ss0 = __shfl_sync(0xffffffffu, s, e + half);
                    int ss1 = __shfl_sync(0xffffffffu, s, e + 2 + half);
                    int ss2 = __shfl_sync(0xffffffffu, s, e + 4 + half);
                    int ss3 = __shfl_sync(0xffffffffu, s, e + 6 + half);
                    uint4 q0 = __ldg(f4 + (size_t)ss0 * 16 + li);
                    uint4 q1 = __ldg(f4 + (size_t)ss1 * 16 + li);
                    uint4 q2 = __ldg(f4 + (size_t)ss2 * 16 + li);
                    uint4 q3 = __ldg(f4 + (size_t)ss3 * 16 + li);
                    __half2* h0 = (__half2*)&q0;
                    __half2* h1 = (__half2*)&q1;
                    __half2* h2 = (__half2*)&q2;
                    __half2* h3 = (__half2*)&q3;
                    #pragma unroll
                    for (int c = 0; c < 4; c++) {
                        __half2 r01 = __hadd2(h0[c], h1[c]);
                        __half2 r23 = __hadd2(h2[c], h3[c]);
                        float2 f01 = __half22float2(r01);
                        float2 f23 = __half22float2(r23);
                        float2* ac = (c == 0) ? &a0 : (c == 1) ? &a1 : (c == 2) ? &a2 : &a3;
                        ac->x += f01.x + f23.x;
                        ac->y += f01.y + f23.y;
                    }
                }
            }
            a0.x += __shfl_xor_sync(0xffffffffu, a0.x, 16);
            a0.y += __shfl_xor_sync(0xffffffffu, a0.y, 16);
            a1.x += __shfl_xor_sync(0xffffffffu, a1.x, 16);
            a1.y += __shfl_xor_sync(0xffffffffu, a1.y, 16);
            a2.x += __shfl_xor_sync(0xffffffffu, a2.x, 16);
            a2.y += __shfl_xor_sync(0xffffffffu, a2.y, 16);
            a3.x += __shfl_xor_sync(0xffffffffu, a3.x, 16);
            a3.y += __shfl_xor_sync(0xffffffffu, a3.y, 16);

            float nmd = g_norm[row] * (1.0f - ALPHA);
            float4 f0 = __ldg((const float4*)feat0 + (size_t)row * 32 + li * 2 + half);
            float4 v;
            if (half == 0) { v.x = a0.x; v.y = a0.y; v.z = a1.x; v.w = a1.y; }
            else           { v.x = a2.x; v.y = a2.y; v.z = a3.x; v.w = a3.y; }
            v.x = v.x * nmd + f0.x * ALPHA;
            v.y = v.y * nmd + f0.y * ALPHA;
            v.z = v.z * nmd + f0.z * ALPHA;
            v.w = v.w * nmd + f0.w * ALPHA;
            uint2 pk;
            pk.x = pack_half2(v.x, v.y);
            pk.y = pack_half2(v.z, v.w);
            *(uint2*)&sh[lrow][li * 8 + half * 4] = pk;
        } else {
            *(uint2*)&sh[lrow][li * 8 + half * 4] = make_uint2(0u, 0u);
        }
    }
    __syncthreads();

    // ---- phase 2: fp16 MMA ----
    const int mw = w & 3;
    const int nq = w >> 2;
    float acc[4][4];
    #pragma unroll
    for (int nt = 0; nt < 4; nt++)
        #pragma unroll
        for (int i = 0; i < 4; i++) acc[nt][i] = 0.f;

    const int lm_row = mw * 16 + (lane & 15);
    const int lm_colh = (lane >> 4) * 8;

    #pragma unroll
    for (int kt = 0; kt < 8; kt++) {
        unsigned a0, a1, a2, a3;
        {
            unsigned addr = (unsigned)__cvta_generic_to_shared(
                &sh[lm_row][kt * 16 + lm_colh]);
            asm volatile(
                "ldmatrix.sync.aligned.m8n8.x4.shared.b16 {%0,%1,%2,%3}, [%4];"
                : "=r"(a0), "=r"(a1), "=r"(a2), "=r"(a3) : "r"(addr));
        }
        const uint2* bp = g_wperm + (kt * 16 + nq * 4) * 32 + lane;
        #pragma unroll
        for (int nt = 0; nt < 4; nt++) {
            uint2 b = __ldg(bp + nt * 32);
            asm volatile(
                "mma.sync.aligned.m16n8k16.row.col.f32.f16.f16.f32 "
                "{%0,%1,%2,%3}, {%4,%5,%6,%7}, {%8,%9}, {%0,%1,%2,%3};"
                : "+f"(acc[nt][0]), "+f"(acc[nt][1]),
                  "+f"(acc[nt][2]), "+f"(acc[nt][3])
                : "r"(a0), "r"(a1), "r"(a2), "r"(a3), "r"(b.x), "r"(b.y));
        }
    }

    const int lr   = mw * 16 + (lane >> 2);
    const int row0 = r0 + lr;
    const int col0 = (lane & 3) * 2;
    #pragma unroll
    for (int nt = 0; nt < 4; nt++) {
        int col = nq * 32 + nt * 8 + col0;
        float b0 = __ldg(&bias[col]);
        float b1 = __ldg(&bias[col + 1]);
        if (row0 < n) {
            float2 o;
            o.x = ONE_MB * __half2float(sh[lr][col])     + BETA * acc[nt][0] + b0;
            o.y = ONE_MB * __half2float(sh[lr][col + 1]) + BETA * acc[nt][1] + b1;
            *(float2*)&out[(size_t)row0 * D + col] = o;
        }
        if (row0 + 8 < n) {
            float2 o;
            o.x = ONE_MB * __half2float(sh[lr + 8][col])     + BETA * acc[nt][2] + b0;
            o.y = ONE_MB * __half2float(sh[lr + 8][col + 1]) + BETA * acc[nt][3] + b1;
            *(float2*)&out[(size_t)(row0 + 8) * D + col] = o;
        }
    }
}

extern "C" void kernel_launch(void* const* d_in, const int* in_sizes, int n_in,
                              void* d_out, int out_size) {
    const float* feat  = (const float*)d_in[0];
    const float* feat0 = (const float*)d_in[1];
    const float* W     = (const float*)d_in[2];
    const float* bias  = (const float*)d_in[3];
    const int*   src   = (const int*)d_in[4];
    const int*   dst   = (const int*)d_in[5];
    float* out = (float*)d_out;

    int n  = in_sizes[0] / D;
    int ne = in_sizes[4];

    int eb4 = (ne + 1023) / 1024;                 // 586 edge blocks
    int degb = (eb4 > 16) ? eb4 : 16;

    deg_kernel<<<degb, 256>>>(dst, W, ne);

    int ab = (n + 255) / 256;                     // 196 allocator blocks
    int pb = (n * 32 + 255) / 256;                // 6250 prescale blocks
    alloc_prescale_kernel<<<ab + pb, 256>>>(feat, n, ab);

    permute_kernel<<<eb4, 256>>>(src, dst, ne, n);

    fused_mma_kernel<<<(n + GROWS - 1) / GROWS, 512>>>(feat0, bias, out, n);
}